// round 11
// baseline (speedup 1.0000x reference)
#include <cuda_runtime.h>
#include <cstdint>

#define N_NODES 100000
#define N_EDGES 1600000
#define IN_DIM  128
#define OUT_DIM 64

#define SCAN_BLK 1024
#define NB_SCAN ((N_NODES + SCAN_BLK - 1) / SCAN_BLK)   // 98

// Scratch (no allocations allowed).
__device__ float g_h[(size_t)N_NODES * OUT_DIM];   // h2 = (x@W)*dis[row], 25.6 MB
__device__ float g_dis[N_NODES];
__device__ int   g_row[N_EDGES];
__device__ int   g_col[N_EDGES];
__device__ int   g_cnt[N_NODES];
__device__ int   g_off[N_NODES];                   // CSR offsets (for agg)
__device__ int   g_cur[N_NODES];                   // offset cursors (for fill)
__device__ int   g_src[N_EDGES];
__device__ int   g_bsum[NB_SCAN];
__device__ int   g_is64;

// ---------------------------------------------------------------------------
// 0) zero counters + dtype detect (block 0)
// ---------------------------------------------------------------------------
__global__ void zero_detect_kernel(const int* __restrict__ ei32) {
    int i = blockIdx.x * blockDim.x + threadIdx.x;
    if (i < N_NODES) g_cnt[i] = 0;

    if (blockIdx.x == 0) {
        __shared__ int s_nz;
        if (threadIdx.x == 0) s_nz = 0;
        __syncthreads();
        int nz = 0;
#pragma unroll
        for (int t = 0; t < 4; t++) {
            int e = threadIdx.x + t * 256;            // first 1024 edge slots
            if (__ldg(&ei32[2 * e + 1]) != 0) nz = 1; // int64 hi-words are 0
        }
        if (nz) atomicOr(&s_nz, 1);
        __syncthreads();
        if (threadIdx.x == 0) g_is64 = s_nz ? 0 : 1;
    }
}

// ---------------------------------------------------------------------------
// 0b) materialize int32 row/col + in-degree count
// ---------------------------------------------------------------------------
__global__ void convert_kernel(const void* __restrict__ ei) {
    int e = blockIdx.x * blockDim.x + threadIdx.x;
    if (e >= N_EDGES) return;
    int row, col;
    if (g_is64) {
        const long long* p = (const long long*)ei;
        row = (int)__ldg(&p[e]);
        col = (int)__ldg(&p[N_EDGES + e]);
    } else {
        const int* p = (const int*)ei;
        row = __ldg(&p[e]);
        col = __ldg(&p[N_EDGES + e]);
    }
    g_row[e] = row;
    g_col[e] = col;
    atomicAdd(&g_cnt[col], 1);
}

// ---------------------------------------------------------------------------
// 1) exclusive prefix scan of g_cnt -> g_off
// ---------------------------------------------------------------------------
__global__ __launch_bounds__(SCAN_BLK) void scan1_kernel() {
    __shared__ int s[SCAN_BLK];
    int tid = threadIdx.x;
    int gid = blockIdx.x * SCAN_BLK + tid;
    int v = (gid < N_NODES) ? g_cnt[gid] : 0;
    s[tid] = v;
    __syncthreads();
#pragma unroll
    for (int d = 1; d < SCAN_BLK; d <<= 1) {
        int t = (tid >= d) ? s[tid - d] : 0;
        __syncthreads();
        s[tid] += t;
        __syncthreads();
    }
    if (gid < N_NODES) g_off[gid] = s[tid] - v;   // exclusive within block
    if (tid == SCAN_BLK - 1) g_bsum[blockIdx.x] = s[tid];
}

// parallel block-scan of the 98 partial sums (1 block, 128 threads)
__global__ __launch_bounds__(128) void scan2_kernel() {
    __shared__ int s[128];
    int tid = threadIdx.x;
    int v = (tid < NB_SCAN) ? g_bsum[tid] : 0;
    s[tid] = v;
    __syncthreads();
#pragma unroll
    for (int d = 1; d < 128; d <<= 1) {
        int t = (tid >= d) ? s[tid - d] : 0;
        __syncthreads();
        s[tid] += t;
        __syncthreads();
    }
    if (tid < NB_SCAN) g_bsum[tid] = s[tid] - v;  // exclusive
}

// scan3: finalize offsets (off + cursor copy) and dis = deg^{-1/2}
__global__ __launch_bounds__(SCAN_BLK) void scan3_kernel() {
    int gid = blockIdx.x * SCAN_BLK + threadIdx.x;
    if (gid < N_NODES) {
        int o = g_off[gid] + g_bsum[blockIdx.x];
        g_off[gid] = o;
        g_cur[gid] = o;
        int c = g_cnt[gid];
        g_dis[gid] = (c > 0) ? rsqrtf((float)c) : 0.f;
    }
}

// ---------------------------------------------------------------------------
// 2) FUSED: tf32 mma GEMM (blocks < GB) + CSR bucket fill (blocks >= GB).
//    Both depend only on scan3; fusing lets them overlap on-chip.
// ---------------------------------------------------------------------------
#define APITCH 132
#define BPITCH 68
#define GSMEM ((128 * APITCH + 128 * BPITCH) * 4)   // 102400 bytes
#define GB ((N_NODES + 127) / 128)                   // 782 gemm blocks
#define FILL_EPT 4
#define FB ((N_EDGES + 128 * FILL_EPT - 1) / (128 * FILL_EPT))   // 3125 fill blocks

__global__ __launch_bounds__(128) void gemm_fill_kernel(const float* __restrict__ x,
                                                        const float* __restrict__ W) {
    if (blockIdx.x >= GB) {
        // ---------------- fill path ----------------
        int ebase = (blockIdx.x - GB) * 128 * FILL_EPT + threadIdx.x;
#pragma unroll
        for (int t = 0; t < FILL_EPT; t++) {
            int e = ebase + t * 128;
            if (e < N_EDGES) {
                int col = __ldg(&g_col[e]);
                int pos = atomicAdd(&g_cur[col], 1);
                g_src[pos] = __ldg(&g_row[e]);
            }
        }
        return;
    }

    // ---------------- gemm path ----------------
    extern __shared__ float sm[];
    float* As = sm;                    // [128][APITCH]
    float* Bs = sm + 128 * APITCH;     // [128][BPITCH]  (k-major: Bs[k][n])

    const int tid  = threadIdx.x;
    const int lane = tid & 31;
    const int w    = tid >> 5;
    const int base = blockIdx.x * 128;
    const int nvalid = min(128, N_NODES - base);

    // stage W (128x64) as tf32 bits
#pragma unroll
    for (int t = 0; t < 16; t++) {
        int i = t * 128 + tid;
        int r = i >> 4;
        int c = (i & 15) * 4;
        float4 v = __ldg((const float4*)(W + r * OUT_DIM + c));
        uint32_t u0, u1, u2, u3;
        asm("cvt.rna.tf32.f32 %0, %1;" : "=r"(u0) : "f"(v.x));
        asm("cvt.rna.tf32.f32 %0, %1;" : "=r"(u1) : "f"(v.y));
        asm("cvt.rna.tf32.f32 %0, %1;" : "=r"(u2) : "f"(v.z));
        asm("cvt.rna.tf32.f32 %0, %1;" : "=r"(u3) : "f"(v.w));
        float* d = Bs + r * BPITCH + c;
        d[0] = __uint_as_float(u0); d[1] = __uint_as_float(u1);
        d[2] = __uint_as_float(u2); d[3] = __uint_as_float(u3);
    }

    // stage x tile (128x128) as tf32 bits, zero-pad invalid rows
#pragma unroll
    for (int t = 0; t < 32; t++) {
        int i = t * 128 + tid;
        int r = i >> 5;
        int c = (i & 31) * 4;
        float4 v = make_float4(0.f, 0.f, 0.f, 0.f);
        if (r < nvalid)
            v = __ldg((const float4*)(x + ((size_t)(base + r) << 7) + c));
        uint32_t u0, u1, u2, u3;
        asm("cvt.rna.tf32.f32 %0, %1;" : "=r"(u0) : "f"(v.x));
        asm("cvt.rna.tf32.f32 %0, %1;" : "=r"(u1) : "f"(v.y));
        asm("cvt.rna.tf32.f32 %0, %1;" : "=r"(u2) : "f"(v.z));
        asm("cvt.rna.tf32.f32 %0, %1;" : "=r"(u3) : "f"(v.w));
        float* d = As + r * APITCH + c;
        d[0] = __uint_as_float(u0); d[1] = __uint_as_float(u1);
        d[2] = __uint_as_float(u2); d[3] = __uint_as_float(u3);
    }
    __syncthreads();

    float acc[2][8][4];
#pragma unroll
    for (int mi = 0; mi < 2; mi++)
#pragma unroll
        for (int ni = 0; ni < 8; ni++)
#pragma unroll
            for (int j = 0; j < 4; j++) acc[mi][ni][j] = 0.f;

    const int arow = w * 32 + (lane >> 2);
    const int acol = lane & 3;
    const int bcol = lane >> 2;
    const int bkof = lane & 3;

#pragma unroll
    for (int kk = 0; kk < 16; kk++) {
        int kb = kk * 8;
        uint32_t a[2][4];
#pragma unroll
        for (int mi = 0; mi < 2; mi++) {
            const float* ap = As + (arow + mi * 16) * APITCH + kb + acol;
            a[mi][0] = __float_as_uint(ap[0]);
            a[mi][1] = __float_as_uint(ap[8 * APITCH]);
            a[mi][2] = __float_as_uint(ap[4]);
            a[mi][3] = __float_as_uint(ap[8 * APITCH + 4]);
        }
        uint32_t bf[8][2];
#pragma unroll
        for (int ni = 0; ni < 8; ni++) {
            const float* bp = Bs + (kb + bkof) * BPITCH + ni * 8 + bcol;
            bf[ni][0] = __float_as_uint(bp[0]);
            bf[ni][1] = __float_as_uint(bp[4 * BPITCH]);
        }
#pragma unroll
        for (int mi = 0; mi < 2; mi++)
#pragma unroll
            for (int ni = 0; ni < 8; ni++) {
                asm volatile(
                    "mma.sync.aligned.m16n8k8.row.col.f32.tf32.tf32.f32 "
                    "{%0, %1, %2, %3}, {%4, %5, %6, %7}, {%8, %9}, {%0, %1, %2, %3};"
                    : "+f"(acc[mi][ni][0]), "+f"(acc[mi][ni][1]),
                      "+f"(acc[mi][ni][2]), "+f"(acc[mi][ni][3])
                    : "r"(a[mi][0]), "r"(a[mi][1]), "r"(a[mi][2]), "r"(a[mi][3]),
                      "r"(bf[ni][0]), "r"(bf[ni][1]));
            }
    }

    // epilogue: scale by dis[row], write g_h
    const int cc = 2 * (lane & 3);
#pragma unroll
    for (int mi = 0; mi < 2; mi++) {
        int ra = base + w * 32 + mi * 16 + (lane >> 2);
        int rb = ra + 8;
        float da = (ra < N_NODES) ? __ldg(&g_dis[ra]) : 0.f;
        float db = (rb < N_NODES) ? __ldg(&g_dis[rb]) : 0.f;
#pragma unroll
        for (int ni = 0; ni < 8; ni++) {
            if (ra < N_NODES) {
                float2 o = make_float2(acc[mi][ni][0] * da, acc[mi][ni][1] * da);
                *(float2*)(g_h + ((size_t)ra << 6) + ni * 8 + cc) = o;
            }
            if (rb < N_NODES) {
                float2 o = make_float2(acc[mi][ni][2] * db, acc[mi][ni][3] * db);
                *(float2*)(g_h + ((size_t)rb << 6) + ni * 8 + cc) = o;
            }
        }
    }
}

// ---------------------------------------------------------------------------
// 3) aggregate: one warp per target node, register accumulation, no atomics
// ---------------------------------------------------------------------------
__global__ __launch_bounds__(256) void agg_kernel(float* __restrict__ out,
                                                  const float* __restrict__ b) {
    int node = (blockIdx.x * blockDim.x + threadIdx.x) >> 5;
    int lane = threadIdx.x & 31;
    if (node >= N_NODES) return;

    int beg = g_off[node];
    int n   = g_cnt[node];

    float2 acc = make_float2(0.f, 0.f);
#pragma unroll 4
    for (int k = 0; k < n; k++) {
        int src = __ldg(&g_src[beg + k]);
        float2 v = __ldg((const float2*)(g_h + ((size_t)src << 6)) + lane);
        acc.x += v.x;
        acc.y += v.y;
    }

    float dc  = g_dis[node];
    float2 bb = __ldg((const float2*)b + lane);
    float2 o;
    o.x = fmaxf(acc.x * dc + bb.x, 0.f);
    o.y = fmaxf(acc.y * dc + bb.y, 0.f);
    ((float2*)(out + ((size_t)node << 6)))[lane] = o;
}

// ---------------------------------------------------------------------------
extern "C" void kernel_launch(void* const* d_in, const int* in_sizes, int n_in,
                              void* d_out, int out_size) {
    const float* x  = 0;
    const void*  ei = 0;
    const float* W  = 0;
    const float* b  = 0;

    for (int i = 0; i < n_in; i++) {
        int sz = in_sizes[i];
        if      (sz == N_NODES * IN_DIM)  x  = (const float*)d_in[i];
        else if (sz == 2 * N_EDGES)       ei = d_in[i];
        else if (sz == IN_DIM * OUT_DIM)  W  = (const float*)d_in[i];
        else if (sz == OUT_DIM)           b  = (const float*)d_in[i];
    }

    float* out = (float*)d_out;
    const int EB  = (N_EDGES + 255) / 256;
    const int NBn = (N_NODES + 255) / 256;

    static int smem_set = 0;
    if (!smem_set) {
        cudaFuncSetAttribute(gemm_fill_kernel,
                             cudaFuncAttributeMaxDynamicSharedMemorySize, GSMEM);
        smem_set = 1;
    }

    zero_detect_kernel<<<NBn, 256>>>((const int*)ei);
    convert_kernel<<<EB, 256>>>(ei);
    scan1_kernel<<<NB_SCAN, SCAN_BLK>>>();
    scan2_kernel<<<1, 128>>>();
    scan3_kernel<<<NB_SCAN, SCAN_BLK>>>();
    gemm_fill_kernel<<<GB + FB, 128, GSMEM>>>(x, W);
    agg_kernel<<<(N_NODES * 32 + 255) / 256, 256>>>(out, b);
}

// round 12
// speedup vs baseline: 1.1759x; 1.1759x over previous
#include <cuda_runtime.h>
#include <cstdint>

#define N_NODES 100000
#define N_EDGES 1600000
#define IN_DIM  128
#define OUT_DIM 64

#define SCAN_BLK 1024
#define NB_SCAN ((N_NODES + SCAN_BLK - 1) / SCAN_BLK)   // 98

// Scratch (no allocations allowed).
__device__ float g_h[(size_t)N_NODES * OUT_DIM];   // h2 = (x@W)*dis[row], 25.6 MB
__device__ float g_dis[N_NODES];
__device__ int   g_row[N_EDGES];
__device__ int   g_col[N_EDGES];
__device__ int   g_cnt[N_NODES];
__device__ int   g_off[N_NODES];                   // CSR offsets (for agg)
__device__ int   g_cur[N_NODES];                   // offset cursors (for fill)
__device__ int   g_src[N_EDGES];
__device__ int   g_state[NB_SCAN];                 // lookback: (value<<2)|status
__device__ int   g_is64;

// ---------------------------------------------------------------------------
// 0) zero counters + scan state + dtype detect (block 0)
// ---------------------------------------------------------------------------
__global__ void zero_detect_kernel(const int* __restrict__ ei32) {
    int i = blockIdx.x * blockDim.x + threadIdx.x;
    if (i < N_NODES) g_cnt[i] = 0;
    if (i < NB_SCAN) g_state[i] = 0;

    if (blockIdx.x == 0) {
        __shared__ int s_nz;
        if (threadIdx.x == 0) s_nz = 0;
        __syncthreads();
        int nz = 0;
#pragma unroll
        for (int t = 0; t < 4; t++) {
            int e = threadIdx.x + t * 256;            // first 1024 edge slots
            if (__ldg(&ei32[2 * e + 1]) != 0) nz = 1; // int64 hi-words are 0
        }
        if (nz) atomicOr(&s_nz, 1);
        __syncthreads();
        if (threadIdx.x == 0) g_is64 = s_nz ? 0 : 1;
    }
}

// ---------------------------------------------------------------------------
// 1) materialize int32 row/col + in-degree count (4 edges/thread, vectorized)
// ---------------------------------------------------------------------------
__global__ void convert_kernel(const void* __restrict__ ei) {
    int e4 = (blockIdx.x * blockDim.x + threadIdx.x) * 4;
    if (e4 >= N_EDGES) return;
    if (g_is64) {
        const long long* p = (const long long*)ei;
#pragma unroll
        for (int t = 0; t < 4; t++) {
            int e = e4 + t;
            int row = (int)__ldg(&p[e]);
            int col = (int)__ldg(&p[N_EDGES + e]);
            g_row[e] = row;
            g_col[e] = col;
            atomicAdd(&g_cnt[col], 1);
        }
    } else {
        const int* p = (const int*)ei;
        int4 r = __ldg((const int4*)(p + e4));
        int4 c = __ldg((const int4*)(p + N_EDGES + e4));
        *(int4*)(g_row + e4) = r;
        *(int4*)(g_col + e4) = c;
        atomicAdd(&g_cnt[c.x], 1);
        atomicAdd(&g_cnt[c.y], 1);
        atomicAdd(&g_cnt[c.z], 1);
        atomicAdd(&g_cnt[c.w], 1);
    }
}

// ---------------------------------------------------------------------------
// 2) single-pass scan (decoupled lookback) + offsets + cursors + dis
//    status: 0=pending, 1=aggregate ready, 2=inclusive prefix ready
// ---------------------------------------------------------------------------
__global__ __launch_bounds__(SCAN_BLK) void scan_kernel() {
    __shared__ int s[SCAN_BLK];
    __shared__ int s_pfx;
    const int tid = threadIdx.x;
    const int bid = blockIdx.x;
    const int gid = bid * SCAN_BLK + tid;

    int v = (gid < N_NODES) ? g_cnt[gid] : 0;
    s[tid] = v;
    __syncthreads();
#pragma unroll
    for (int d = 1; d < SCAN_BLK; d <<= 1) {
        int t = (tid >= d) ? s[tid - d] : 0;
        __syncthreads();
        s[tid] += t;
        __syncthreads();
    }
    const int incl = s[tid];           // inclusive local scan
    const int agg  = s[SCAN_BLK - 1];  // block total

    if (tid < 32) {
        if (bid == 0) {
            if (tid == 0) {
                atomicExch(&g_state[0], (agg << 2) | 2);
                s_pfx = 0;
            }
        } else {
            if (tid == 0)
                atomicExch(&g_state[bid], (agg << 2) | 1);  // publish aggregate early
            // warp-parallel lookback, 32 predecessors per round
            int pfx = 0;
            int j = bid - 1;
            for (;;) {
                int idx = j - tid;
                int st = 0;
                if (idx >= 0) {
                    do { st = atomicAdd(&g_state[idx], 0); } while ((st & 3) == 0);
                }
                unsigned m2 = __ballot_sync(0xffffffffu, (idx >= 0) && ((st & 3) == 2));
                int stop = m2 ? (__ffs(m2) - 1) : 32;   // lowest lane with prefix-ready
                int contrib = (idx >= 0 && tid <= stop) ? (st >> 2) : 0;
#pragma unroll
                for (int o = 16; o; o >>= 1)
                    contrib += __shfl_down_sync(0xffffffffu, contrib, o);
                if (tid == 0) pfx += contrib;
                if (m2 || j < 32) break;
                j -= 32;
            }
            if (tid == 0) {
                atomicExch(&g_state[bid], ((agg + pfx) << 2) | 2);
                s_pfx = pfx;
            }
        }
    }
    __syncthreads();

    if (gid < N_NODES) {
        int o = s_pfx + incl - v;      // exclusive global prefix
        g_off[gid] = o;
        g_cur[gid] = o;
        g_dis[gid] = (v > 0) ? rsqrtf((float)v) : 0.f;
    }
}

// ---------------------------------------------------------------------------
// 3) GEMM via legacy mma.sync tf32: h2[128,64] = (x_tile @ W) * dis[row]
// ---------------------------------------------------------------------------
#define APITCH 132
#define BPITCH 68
#define GSMEM ((128 * APITCH + 128 * BPITCH) * 4)   // 102400 bytes
#define GB ((N_NODES + 127) / 128)                   // 782

__global__ __launch_bounds__(128) void gemm_mma_kernel(const float* __restrict__ x,
                                                       const float* __restrict__ W) {
    extern __shared__ float sm[];
    float* As = sm;                    // [128][APITCH]
    float* Bs = sm + 128 * APITCH;     // [128][BPITCH]  (k-major: Bs[k][n])

    const int tid  = threadIdx.x;
    const int lane = tid & 31;
    const int w    = tid >> 5;
    const int base = blockIdx.x * 128;
    const int nvalid = min(128, N_NODES - base);

    // stage W (128x64) as tf32 bits
#pragma unroll
    for (int t = 0; t < 16; t++) {
        int i = t * 128 + tid;
        int r = i >> 4;
        int c = (i & 15) * 4;
        float4 v = __ldg((const float4*)(W + r * OUT_DIM + c));
        uint32_t u0, u1, u2, u3;
        asm("cvt.rna.tf32.f32 %0, %1;" : "=r"(u0) : "f"(v.x));
        asm("cvt.rna.tf32.f32 %0, %1;" : "=r"(u1) : "f"(v.y));
        asm("cvt.rna.tf32.f32 %0, %1;" : "=r"(u2) : "f"(v.z));
        asm("cvt.rna.tf32.f32 %0, %1;" : "=r"(u3) : "f"(v.w));
        float* d = Bs + r * BPITCH + c;
        d[0] = __uint_as_float(u0); d[1] = __uint_as_float(u1);
        d[2] = __uint_as_float(u2); d[3] = __uint_as_float(u3);
    }

    // stage x tile (128x128) as tf32 bits, zero-pad invalid rows
#pragma unroll
    for (int t = 0; t < 32; t++) {
        int i = t * 128 + tid;
        int r = i >> 5;
        int c = (i & 31) * 4;
        float4 v = make_float4(0.f, 0.f, 0.f, 0.f);
        if (r < nvalid)
            v = __ldg((const float4*)(x + ((size_t)(base + r) << 7) + c));
        uint32_t u0, u1, u2, u3;
        asm("cvt.rna.tf32.f32 %0, %1;" : "=r"(u0) : "f"(v.x));
        asm("cvt.rna.tf32.f32 %0, %1;" : "=r"(u1) : "f"(v.y));
        asm("cvt.rna.tf32.f32 %0, %1;" : "=r"(u2) : "f"(v.z));
        asm("cvt.rna.tf32.f32 %0, %1;" : "=r"(u3) : "f"(v.w));
        float* d = As + r * APITCH + c;
        d[0] = __uint_as_float(u0); d[1] = __uint_as_float(u1);
        d[2] = __uint_as_float(u2); d[3] = __uint_as_float(u3);
    }
    __syncthreads();

    float acc[2][8][4];
#pragma unroll
    for (int mi = 0; mi < 2; mi++)
#pragma unroll
        for (int ni = 0; ni < 8; ni++)
#pragma unroll
            for (int j = 0; j < 4; j++) acc[mi][ni][j] = 0.f;

    const int arow = w * 32 + (lane >> 2);
    const int acol = lane & 3;
    const int bcol = lane >> 2;
    const int bkof = lane & 3;

#pragma unroll
    for (int kk = 0; kk < 16; kk++) {
        int kb = kk * 8;
        uint32_t a[2][4];
#pragma unroll
        for (int mi = 0; mi < 2; mi++) {
            const float* ap = As + (arow + mi * 16) * APITCH + kb + acol;
            a[mi][0] = __float_as_uint(ap[0]);
            a[mi][1] = __float_as_uint(ap[8 * APITCH]);
            a[mi][2] = __float_as_uint(ap[4]);
            a[mi][3] = __float_as_uint(ap[8 * APITCH + 4]);
        }
        uint32_t bf[8][2];
#pragma unroll
        for (int ni = 0; ni < 8; ni++) {
            const float* bp = Bs + (kb + bkof) * BPITCH + ni * 8 + bcol;
            bf[ni][0] = __float_as_uint(bp[0]);
            bf[ni][1] = __float_as_uint(bp[4 * BPITCH]);
        }
#pragma unroll
        for (int mi = 0; mi < 2; mi++)
#pragma unroll
            for (int ni = 0; ni < 8; ni++) {
                asm volatile(
                    "mma.sync.aligned.m16n8k8.row.col.f32.tf32.tf32.f32 "
                    "{%0, %1, %2, %3}, {%4, %5, %6, %7}, {%8, %9}, {%0, %1, %2, %3};"
                    : "+f"(acc[mi][ni][0]), "+f"(acc[mi][ni][1]),
                      "+f"(acc[mi][ni][2]), "+f"(acc[mi][ni][3])
                    : "r"(a[mi][0]), "r"(a[mi][1]), "r"(a[mi][2]), "r"(a[mi][3]),
                      "r"(bf[ni][0]), "r"(bf[ni][1]));
            }
    }

    // epilogue: scale by dis[row], write g_h
    const int cc = 2 * (lane & 3);
#pragma unroll
    for (int mi = 0; mi < 2; mi++) {
        int ra = base + w * 32 + mi * 16 + (lane >> 2);
        int rb = ra + 8;
        float da = (ra < N_NODES) ? __ldg(&g_dis[ra]) : 0.f;
        float db = (rb < N_NODES) ? __ldg(&g_dis[rb]) : 0.f;
#pragma unroll
        for (int ni = 0; ni < 8; ni++) {
            if (ra < N_NODES) {
                float2 o = make_float2(acc[mi][ni][0] * da, acc[mi][ni][1] * da);
                *(float2*)(g_h + ((size_t)ra << 6) + ni * 8 + cc) = o;
            }
            if (rb < N_NODES) {
                float2 o = make_float2(acc[mi][ni][2] * db, acc[mi][ni][3] * db);
                *(float2*)(g_h + ((size_t)rb << 6) + ni * 8 + cc) = o;
            }
        }
    }
}

// ---------------------------------------------------------------------------
// 4) bucket fill (CSR by target), 4 edges/thread
// ---------------------------------------------------------------------------
__global__ void fill_kernel() {
    int e4 = (blockIdx.x * blockDim.x + threadIdx.x) * 4;
    if (e4 >= N_EDGES) return;
    int4 c = *(const int4*)(g_col + e4);
    int4 r = *(const int4*)(g_row + e4);
    int p0 = atomicAdd(&g_cur[c.x], 1); g_src[p0] = r.x;
    int p1 = atomicAdd(&g_cur[c.y], 1); g_src[p1] = r.y;
    int p2 = atomicAdd(&g_cur[c.z], 1); g_src[p2] = r.z;
    int p3 = atomicAdd(&g_cur[c.w], 1); g_src[p3] = r.w;
}

// ---------------------------------------------------------------------------
// 5) aggregate: one warp per node, 16 lanes x float4 per row, 2 edges/iter.
//    Half-warp g handles edges k=g, g+2, g+4, ...; shfl-combine at the end.
// ---------------------------------------------------------------------------
__global__ __launch_bounds__(256) void agg_kernel(float* __restrict__ out,
                                                  const float* __restrict__ b) {
    int node = (blockIdx.x * blockDim.x + threadIdx.x) >> 5;
    int lane = threadIdx.x & 31;
    if (node >= N_NODES) return;
    int g   = lane >> 4;     // half-warp: 0 or 1
    int sub = lane & 15;     // float4 slot within the 64-col row

    int beg = g_off[node];
    int n   = g_cnt[node];

    float4 acc = make_float4(0.f, 0.f, 0.f, 0.f);
    for (int k = g; k < n; k += 2) {
        int src = __ldg(&g_src[beg + k]);
        float4 v = __ldg((const float4*)(g_h + ((size_t)src << 6)) + sub);
        acc.x += v.x; acc.y += v.y; acc.z += v.z; acc.w += v.w;
    }

    // combine half-warps: lanes 0-15 += lanes 16-31 (same sub, other edge parity)
    acc.x += __shfl_down_sync(0xffffffffu, acc.x, 16);
    acc.y += __shfl_down_sync(0xffffffffu, acc.y, 16);
    acc.z += __shfl_down_sync(0xffffffffu, acc.z, 16);
    acc.w += __shfl_down_sync(0xffffffffu, acc.w, 16);

    if (g == 0) {
        float dc  = g_dis[node];
        float4 bb = __ldg((const float4*)b + sub);
        float4 o;
        o.x = fmaxf(acc.x * dc + bb.x, 0.f);
        o.y = fmaxf(acc.y * dc + bb.y, 0.f);
        o.z = fmaxf(acc.z * dc + bb.z, 0.f);
        o.w = fmaxf(acc.w * dc + bb.w, 0.f);
        ((float4*)(out + ((size_t)node << 6)))[sub] = o;
    }
}

// ---------------------------------------------------------------------------
extern "C" void kernel_launch(void* const* d_in, const int* in_sizes, int n_in,
                              void* d_out, int out_size) {
    const float* x  = 0;
    const void*  ei = 0;
    const float* W  = 0;
    const float* b  = 0;

    for (int i = 0; i < n_in; i++) {
        int sz = in_sizes[i];
        if      (sz == N_NODES * IN_DIM)  x  = (const float*)d_in[i];
        else if (sz == 2 * N_EDGES)       ei = d_in[i];
        else if (sz == IN_DIM * OUT_DIM)  W  = (const float*)d_in[i];
        else if (sz == OUT_DIM)           b  = (const float*)d_in[i];
    }

    float* out = (float*)d_out;
    const int NBn = (N_NODES + 255) / 256;
    const int EB4 = (N_EDGES / 4 + 255) / 256;   // 4 edges/thread kernels

    static int smem_set = 0;
    if (!smem_set) {
        cudaFuncSetAttribute(gemm_mma_kernel,
                             cudaFuncAttributeMaxDynamicSharedMemorySize, GSMEM);
        smem_set = 1;
    }

    zero_detect_kernel<<<NBn, 256>>>((const int*)ei);
    convert_kernel<<<EB4, 256>>>(ei);
    scan_kernel<<<NB_SCAN, SCAN_BLK>>>();
    gemm_mma_kernel<<<GB, 128, GSMEM>>>(x, W);
    fill_kernel<<<EB4, 256>>>();
    agg_kernel<<<(N_NODES * 32 + 255) / 256, 256>>>(out, b);
}

// round 17
// speedup vs baseline: 1.1996x; 1.0202x over previous
#include <cuda_runtime.h>
#include <cstdint>

#define N_NODES 100000
#define N_EDGES 1600000
#define IN_DIM  128
#define OUT_DIM 64

#define SCAN_BLK 1024
#define NB_SCAN ((N_NODES + SCAN_BLK - 1) / SCAN_BLK)   // 98

// Scratch (no allocations allowed).
__device__ float g_h[(size_t)N_NODES * OUT_DIM];   // h2 = (x@W)*dis[row], 25.6 MB
__device__ float g_dis[N_NODES];
__device__ int   g_row[N_EDGES];
__device__ int   g_col[N_EDGES];
__device__ int   g_cnt[N_NODES];
__device__ int   g_off[N_NODES];                   // CSR offsets (for agg)
__device__ int   g_cur[N_NODES];                   // offset cursors (for fill)
__device__ int   g_src[N_EDGES];
__device__ int   g_state[NB_SCAN];                 // lookback: (value<<2)|status
__device__ int   g_is64;

// ---------------------------------------------------------------------------
// 0) zero counters + scan state + dtype detect (block 0)
// ---------------------------------------------------------------------------
__global__ void zero_detect_kernel(const int* __restrict__ ei32) {
    int i = blockIdx.x * blockDim.x + threadIdx.x;
    if (i < N_NODES) g_cnt[i] = 0;
    if (i < NB_SCAN) g_state[i] = 0;

    if (blockIdx.x == 0) {
        __shared__ int s_nz;
        if (threadIdx.x == 0) s_nz = 0;
        __syncthreads();
        int nz = 0;
#pragma unroll
        for (int t = 0; t < 4; t++) {
            int e = threadIdx.x + t * 256;            // first 1024 edge slots
            if (__ldg(&ei32[2 * e + 1]) != 0) nz = 1; // int64 hi-words are 0
        }
        if (nz) atomicOr(&s_nz, 1);
        __syncthreads();
        if (threadIdx.x == 0) g_is64 = s_nz ? 0 : 1;
    }
}

// ---------------------------------------------------------------------------
// 1) materialize int32 row/col + in-degree count (4 edges/thread, vectorized)
// ---------------------------------------------------------------------------
__global__ void convert_kernel(const void* __restrict__ ei) {
    int e4 = (blockIdx.x * blockDim.x + threadIdx.x) * 4;
    if (e4 >= N_EDGES) return;
    if (g_is64) {
        const long long* p = (const long long*)ei;
#pragma unroll
        for (int t = 0; t < 4; t++) {
            int e = e4 + t;
            int row = (int)__ldg(&p[e]);
            int col = (int)__ldg(&p[N_EDGES + e]);
            g_row[e] = row;
            g_col[e] = col;
            atomicAdd(&g_cnt[col], 1);
        }
    } else {
        const int* p = (const int*)ei;
        int4 r = __ldg((const int4*)(p + e4));
        int4 c = __ldg((const int4*)(p + N_EDGES + e4));
        *(int4*)(g_row + e4) = r;
        *(int4*)(g_col + e4) = c;
        atomicAdd(&g_cnt[c.x], 1);
        atomicAdd(&g_cnt[c.y], 1);
        atomicAdd(&g_cnt[c.z], 1);
        atomicAdd(&g_cnt[c.w], 1);
    }
}

// ---------------------------------------------------------------------------
// 2) single-pass scan (decoupled lookback) + offsets + cursors + dis
// ---------------------------------------------------------------------------
__global__ __launch_bounds__(SCAN_BLK) void scan_kernel() {
    __shared__ int s[SCAN_BLK];
    __shared__ int s_pfx;
    const int tid = threadIdx.x;
    const int bid = blockIdx.x;
    const int gid = bid * SCAN_BLK + tid;

    int v = (gid < N_NODES) ? g_cnt[gid] : 0;
    s[tid] = v;
    __syncthreads();
#pragma unroll
    for (int d = 1; d < SCAN_BLK; d <<= 1) {
        int t = (tid >= d) ? s[tid - d] : 0;
        __syncthreads();
        s[tid] += t;
        __syncthreads();
    }
    const int incl = s[tid];
    const int agg  = s[SCAN_BLK - 1];

    if (tid < 32) {
        if (bid == 0) {
            if (tid == 0) {
                atomicExch(&g_state[0], (agg << 2) | 2);
                s_pfx = 0;
            }
        } else {
            if (tid == 0)
                atomicExch(&g_state[bid], (agg << 2) | 1);
            int pfx = 0;
            int j = bid - 1;
            for (;;) {
                int idx = j - tid;
                int st = 0;
                if (idx >= 0) {
                    do { st = atomicAdd(&g_state[idx], 0); } while ((st & 3) == 0);
                }
                unsigned m2 = __ballot_sync(0xffffffffu, (idx >= 0) && ((st & 3) == 2));
                int stop = m2 ? (__ffs(m2) - 1) : 32;
                int contrib = (idx >= 0 && tid <= stop) ? (st >> 2) : 0;
#pragma unroll
                for (int o = 16; o; o >>= 1)
                    contrib += __shfl_down_sync(0xffffffffu, contrib, o);
                if (tid == 0) pfx += contrib;
                if (m2 || j < 32) break;
                j -= 32;
            }
            if (tid == 0) {
                atomicExch(&g_state[bid], ((agg + pfx) << 2) | 2);
                s_pfx = pfx;
            }
        }
    }
    __syncthreads();

    if (gid < N_NODES) {
        int o = s_pfx + incl - v;
        g_off[gid] = o;
        g_cur[gid] = o;
        g_dis[gid] = (v > 0) ? rsqrtf((float)v) : 0.f;
    }
}

// ---------------------------------------------------------------------------
// 3) GEMM via mma.sync tf32, 256 threads, K-chunked double-buffered A.
//    h2[128,64] = (x_tile @ W) * dis[row]
//    8 warps, warp w owns rows w*16..w*16+15 (one m16 strip, 8 n8 tiles).
// ---------------------------------------------------------------------------
#define KC      32
#define APITCH  36
#define BPITCH  72
#define GSMEM  ((128 * BPITCH + 2 * 128 * APITCH) * 4)   // 73728 bytes
#define GB ((N_NODES + 127) / 128)                        // 782

__global__ __launch_bounds__(256, 3) void gemm_mma_kernel(const float* __restrict__ x,
                                                          const float* __restrict__ W) {
    extern __shared__ float sm[];
    float* Bs = sm;                        // [128][BPITCH] k-major
    float* As = sm + 128 * BPITCH;         // [2][128][APITCH]

    const int tid  = threadIdx.x;
    const int lane = tid & 31;
    const int w    = tid >> 5;             // 0..7
    const int base = blockIdx.x * 128;
    const int nvalid = min(128, N_NODES - base);

    // ---- stage W (128x64) as tf32, pitch 72 (bank-conflict-free frags) ----
#pragma unroll
    for (int t = 0; t < 8; t++) {
        int i = t * 256 + tid;             // 0..2047 float4 slots
        int r = i >> 4;                    // k row
        int c = (i & 15) * 4;              // n col
        float4 v = __ldg((const float4*)(W + r * OUT_DIM + c));
        uint32_t u0, u1, u2, u3;
        asm("cvt.rna.tf32.f32 %0, %1;" : "=r"(u0) : "f"(v.x));
        asm("cvt.rna.tf32.f32 %0, %1;" : "=r"(u1) : "f"(v.y));
        asm("cvt.rna.tf32.f32 %0, %1;" : "=r"(u2) : "f"(v.z));
        asm("cvt.rna.tf32.f32 %0, %1;" : "=r"(u3) : "f"(v.w));
        float* d = Bs + r * BPITCH + c;
        d[0] = __uint_as_float(u0); d[1] = __uint_as_float(u1);
        d[2] = __uint_as_float(u2); d[3] = __uint_as_float(u3);
    }

    // ---- A chunk loader: rows 0..127, cols kc*32..+31 -> As[buf] ----
    auto load_chunk = [&](int kc, int buf) {
        float* dst = As + buf * 128 * APITCH;
#pragma unroll
        for (int t = 0; t < 4; t++) {
            int i = t * 256 + tid;         // 0..1023 float4 slots
            int r = i >> 3;                // row 0..127
            int c = (i & 7) * 4;           // col 0..28
            float4 v = make_float4(0.f, 0.f, 0.f, 0.f);
            if (r < nvalid)
                v = __ldg((const float4*)(x + ((size_t)(base + r) << 7) + kc * KC + c));
            uint32_t u0, u1, u2, u3;
            asm("cvt.rna.tf32.f32 %0, %1;" : "=r"(u0) : "f"(v.x));
            asm("cvt.rna.tf32.f32 %0, %1;" : "=r"(u1) : "f"(v.y));
            asm("cvt.rna.tf32.f32 %0, %1;" : "=r"(u2) : "f"(v.z));
            asm("cvt.rna.tf32.f32 %0, %1;" : "=r"(u3) : "f"(v.w));
            float* d = dst + r * APITCH + c;
            d[0] = __uint_as_float(u0); d[1] = __uint_as_float(u1);
            d[2] = __uint_as_float(u2); d[3] = __uint_as_float(u3);
        }
    };

    float acc[8][4];
#pragma unroll
    for (int ni = 0; ni < 8; ni++)
#pragma unroll
        for (int j = 0; j < 4; j++) acc[ni][j] = 0.f;

    const int arow = w * 16 + (lane >> 2);
    const int acol = lane & 3;
    const int bcol = lane >> 2;
    const int bkof = lane & 3;

    load_chunk(0, 0);
    __syncthreads();

    int buf = 0;
#pragma unroll
    for (int kc = 0; kc < 4; kc++) {
        if (kc < 3) load_chunk(kc + 1, buf ^ 1);   // overlaps with mma below

        const float* Ab = As + buf * 128 * APITCH;
#pragma unroll
        for (int ks = 0; ks < 4; ks++) {
            int kb = ks * 8;
            uint32_t a0, a1, a2, a3;
            const float* ap = Ab + arow * APITCH + kb + acol;
            a0 = __float_as_uint(ap[0]);
            a1 = __float_as_uint(ap[8 * APITCH]);
            a2 = __float_as_uint(ap[4]);
            a3 = __float_as_uint(ap[8 * APITCH + 4]);
#pragma unroll
            for (int ni = 0; ni < 8; ni++) {
                const float* bp = Bs + (kc * KC + kb + bkof) * BPITCH + ni * 8 + bcol;
                uint32_t b0 = __float_as_uint(bp[0]);
                uint32_t b1 = __float_as_uint(bp[4 * BPITCH]);
                asm volatile(
                    "mma.sync.aligned.m16n8k8.row.col.f32.tf32.tf32.f32 "
                    "{%0, %1, %2, %3}, {%4, %5, %6, %7}, {%8, %9}, {%0, %1, %2, %3};"
                    : "+f"(acc[ni][0]), "+f"(acc[ni][1]),
                      "+f"(acc[ni][2]), "+f"(acc[ni][3])
                    : "r"(a0), "r"(a1), "r"(a2), "r"(a3), "r"(b0), "r"(b1));
            }
        }
        __syncthreads();
        buf ^= 1;
    }

    // ---- epilogue: scale by dis[row], write g_h ----
    const int cc = 2 * (lane & 3);
    int ra = base + w * 16 + (lane >> 2);
    int rb = ra + 8;
    float da = (ra < N_NODES) ? __ldg(&g_dis[ra]) : 0.f;
    float db = (rb < N_NODES) ? __ldg(&g_dis[rb]) : 0.f;
#pragma unroll
    for (int ni = 0; ni < 8; ni++) {
        if (ra < N_NODES) {
            float2 o = make_float2(acc[ni][0] * da, acc[ni][1] * da);
            *(float2*)(g_h + ((size_t)ra << 6) + ni * 8 + cc) = o;
        }
        if (rb < N_NODES) {
            float2 o = make_float2(acc[ni][2] * db, acc[ni][3] * db);
            *(float2*)(g_h + ((size_t)rb << 6) + ni * 8 + cc) = o;
        }
    }
}

// ---------------------------------------------------------------------------
// 4) bucket fill (CSR by target), 4 edges/thread
// ---------------------------------------------------------------------------
__global__ void fill_kernel() {
    int e4 = (blockIdx.x * blockDim.x + threadIdx.x) * 4;
    if (e4 >= N_EDGES) return;
    int4 c = *(const int4*)(g_col + e4);
    int4 r = *(const int4*)(g_row + e4);
    int p0 = atomicAdd(&g_cur[c.x], 1); g_src[p0] = r.x;
    int p1 = atomicAdd(&g_cur[c.y], 1); g_src[p1] = r.y;
    int p2 = atomicAdd(&g_cur[c.z], 1); g_src[p2] = r.z;
    int p3 = atomicAdd(&g_cur[c.w], 1); g_src[p3] = r.w;
}

// ---------------------------------------------------------------------------
// 5) aggregate: one warp per node, 16 lanes x float4 per row, 2 edges/iter
// ---------------------------------------------------------------------------
__global__ __launch_bounds__(256) void agg_kernel(float* __restrict__ out,
                                                  const float* __restrict__ b) {
    int node = (blockIdx.x * blockDim.x + threadIdx.x) >> 5;
    int lane = threadIdx.x & 31;
    if (node >= N_NODES) return;
    int g   = lane >> 4;
    int sub = lane & 15;

    int beg = g_off[node];
    int n   = g_cnt[node];

    float4 acc = make_float4(0.f, 0.f, 0.f, 0.f);
    for (int k = g; k < n; k += 2) {
        int src = __ldg(&g_src[beg + k]);
        float4 v = __ldg((const float4*)(g_h + ((size_t)src << 6)) + sub);
        acc.x += v.x; acc.y += v.y; acc.z += v.z; acc.w += v.w;
    }

    acc.x += __shfl_down_sync(0xffffffffu, acc.x, 16);
    acc.y += __shfl_down_sync(0xffffffffu, acc.y, 16);
    acc.z += __shfl_down_sync(0xffffffffu, acc.z, 16);
    acc.w += __shfl_down_sync(0xffffffffu, acc.w, 16);

    if (g == 0) {
        float dc  = g_dis[node];
        float4 bb = __ldg((const float4*)b + sub);
        float4 o;
        o.x = fmaxf(acc.x * dc + bb.x, 0.f);
        o.y = fmaxf(acc.y * dc + bb.y, 0.f);
        o.z = fmaxf(acc.z * dc + bb.z, 0.f);
        o.w = fmaxf(acc.w * dc + bb.w, 0.f);
        ((float4*)(out + ((size_t)node << 6)))[sub] = o;
    }
}

// ---------------------------------------------------------------------------
extern "C" void kernel_launch(void* const* d_in, const int* in_sizes, int n_in,
                              void* d_out, int out_size) {
    const float* x  = 0;
    const void*  ei = 0;
    const float* W  = 0;
    const float* b  = 0;

    for (int i = 0; i < n_in; i++) {
        int sz = in_sizes[i];
        if      (sz == N_NODES * IN_DIM)  x  = (const float*)d_in[i];
        else if (sz == 2 * N_EDGES)       ei = d_in[i];
        else if (sz == IN_DIM * OUT_DIM)  W  = (const float*)d_in[i];
        else if (sz == OUT_DIM)           b  = (const float*)d_in[i];
    }

    float* out = (float*)d_out;
    const int NBn = (N_NODES + 255) / 256;
    const int EB4 = (N_EDGES / 4 + 255) / 256;

    static int smem_set = 0;
    if (!smem_set) {
        cudaFuncSetAttribute(gemm_mma_kernel,
                             cudaFuncAttributeMaxDynamicSharedMemorySize, GSMEM);
        smem_set = 1;
    }

    zero_detect_kernel<<<NBn, 256>>>((const int*)ei);
    convert_kernel<<<EB4, 256>>>(ei);
    scan_kernel<<<NB_SCAN, SCAN_BLK>>>();
    gemm_mma_kernel<<<GB, 256, GSMEM>>>(x, W);
    fill_kernel<<<EB4, 256>>>();
    agg_kernel<<<(N_NODES * 32 + 255) / 256, 256>>>(out, b);
}